// round 15
// baseline (speedup 1.0000x reference)
#include <cuda_runtime.h>
#include <cstdint>

// ---------------- smem float offsets (32-row tile, 128 threads) ----------------
#define XMF 0                    // 32 x 260 plane: tanh-staged x | tanh(m), later h1
#define RB  8320                 // region: action buffers / msg overlays (18432 floats)
#define BUF(w,s) (RB + ((s)*4+(w))*2304)   // 8 buffers of 64x36
#define F1W  RB                  // 64x132, live P0->P1
#define F2W  RB                  // 64x196, live P2->P3 (after F1W dead)
#define F3W  (RB+12544)          // 32x68,  live P2->P4
#define ZB   (RB+14720)          // 32x68: z (P2->P3), then z2 (P3->P4)
#define MSGR (RB+9216)           // 32x36, live P4->P5 (warp0 slot1, written later)
#define PF1B 26752
#define PF2B 26816
#define PF3B 26880
#define PB1  26912
#define PB2  27168
#define PW3  27424
#define PB3  27680
#define SMACT 27684
#define SSQ  27716
#define SMEMF 27748
#define SMEMB (SMEMF*4)

// pre-rounded (tf32-rna) weights in device scratch
#define GF1 0
#define GF2 8192
#define GF3 20480
#define GW1 22528
#define GW2 88064
__device__ __align__(16) float g_wr[153600];

__device__ __forceinline__ float rt(float x){
    uint32_t u; asm("cvt.rna.tf32.f32 %0, %1;" : "=r"(u) : "f"(x));
    return __uint_as_float(u);
}
__device__ __forceinline__ uint32_t smem_u32(const void* p){
    uint32_t a;
    asm("{ .reg .u64 t; cvta.to.shared.u64 t, %1; cvt.u32.u64 %0, t; }" : "=r"(a) : "l"(p));
    return a;
}
__device__ __forceinline__ void mma8(float* d, uint32_t a0,uint32_t a1,uint32_t a2,uint32_t a3,
                                     uint32_t b0,uint32_t b1){
    asm("mma.sync.aligned.m16n8k8.row.col.f32.tf32.tf32.f32 "
        "{%0,%1,%2,%3},{%4,%5,%6,%7},{%8,%9},{%0,%1,%2,%3};"
        : "+f"(d[0]),"+f"(d[1]),"+f"(d[2]),"+f"(d[3])
        : "r"(a0),"r"(a1),"r"(a2),"r"(a3),"r"(b0),"r"(b1));
}
// msg tile: m16 x (NS*8), K=KS*8, strides AS/WS (% 32 == 4 -> conflict-free)
template<int KS,int NS,int AS,int WS>
__device__ __forceinline__ void mt(float (&acc)[4][4], const float* A, const float* W){
    const int lane = threadIdx.x & 31, g = lane >> 2, l4 = lane & 3;
    const uint32_t* a = (const uint32_t*)(A + g*AS + l4);
    const uint32_t* w = (const uint32_t*)(W + g*WS + l4);
    #pragma unroll 8
    for (int k = 0; k < KS; k++) {
        uint32_t a0=a[0], a1=a[8*AS], a2=a[4], a3=a[8*AS+4];
        #pragma unroll
        for (int n = 0; n < NS; n++)
            mma8(acc[n], a0,a1,a2,a3, w[n*8*WS], w[n*8*WS+4]);
        a += 8; w += 8;
    }
}
// action tile: m32 x n64, one k32 chunk. A stride 260 (XM), W stride 36.
__device__ __forceinline__ void mma32x64(float (&acc)[2][8][4], const float* A, const float* W){
    const int lane = threadIdx.x & 31, g = lane >> 2, l4 = lane & 3;
    const uint32_t* a = (const uint32_t*)(A + g*260 + l4);
    const uint32_t* w = (const uint32_t*)(W + g*36 + l4);
    #pragma unroll
    for (int k = 0; k < 4; k++) {
        uint32_t av[2][4];
        #pragma unroll
        for (int s = 0; s < 2; s++) {
            av[s][0]=a[s*16*260];   av[s][1]=a[(s*16+8)*260];
            av[s][2]=a[s*16*260+4]; av[s][3]=a[(s*16+8)*260+4];
        }
        #pragma unroll
        for (int t = 0; t < 8; t++) {
            uint32_t b0 = w[t*8*36], b1 = w[t*8*36+4];
            #pragma unroll
            for (int s = 0; s < 2; s++)
                mma8(acc[s][t], av[s][0],av[s][1],av[s][2],av[s][3], b0,b1);
        }
        a += 8; w += 8;
    }
}
// one warp streams a 64(n) x 32(k) chunk (gmem row stride 256) into a 64x36 buffer
__device__ __forceinline__ void ldq(uint32_t sdst, const float* g, int lane){
    #pragma unroll
    for (int i = 0; i < 16; i++) {
        int idx = lane + i*32;
        int row = idx >> 3, seg = idx & 7;
        uint32_t d = sdst + (uint32_t)(row*36 + seg*4)*4u;
        asm volatile("cp.async.cg.shared.global [%0], [%1], 16;"
                     :: "r"(d), "l"(g + row*256 + seg*4));
    }
    asm volatile("cp.async.commit_group;" ::: "memory");
}
#define CPWAIT1() asm volatile("cp.async.wait_group 1;" ::: "memory")
#define CPWAIT0() asm volatile("cp.async.wait_group 0;" ::: "memory")

__global__ void prep_weights(const float* f1w, const float* f2w, const float* f3w,
                             const float* w1, const float* w2){
    int i = blockIdx.x*blockDim.x + threadIdx.x, n = gridDim.x*blockDim.x;
    for (int k=i; k<8192;  k+=n) g_wr[GF1+k] = rt(f1w[k]);
    for (int k=i; k<12288; k+=n) g_wr[GF2+k] = rt(f2w[k]);
    for (int k=i; k<2048;  k+=n) g_wr[GF3+k] = rt(f3w[k]);
    for (int k=i; k<65536; k+=n) g_wr[GW1+k] = rt(w1[k]);
    for (int k=i; k<65536; k+=n) g_wr[GW2+k] = rt(w2[k]);
}

__global__ void __launch_bounds__(128, 2)
actor_kernel(const float* __restrict__ x,  const float* __restrict__ m,
             const float* __restrict__ f1b, const float* __restrict__ f2b,
             const float* __restrict__ f3b,
             const float* __restrict__ b1,  const float* __restrict__ b2,
             const float* __restrict__ w3,  const float* __restrict__ b3,
             float* __restrict__ out, int Bn)
{
    extern __shared__ float sm[];
    const uint32_t sbu = smem_u32(sm);
    const int tid = threadIdx.x, wid = tid >> 5, lane = tid & 31;
    const int g = lane >> 2, l4 = lane & 3;
    const long r0 = (long)blockIdx.x * 32;
    const float* wsl1 = g_wr + GW1 + wid*16384;   // this warp's W1 rows [wid*64, +64)
    const float* wsl2 = g_wr + GW2 + wid*16384;

    // ---------------- P0: params + inputs + f1w ----------------
    if (tid < 64) { sm[PF1B+tid]=f1b[tid]; sm[PF2B+tid]=f2b[tid]; }
    if (tid < 32) { sm[PF3B+tid]=f3b[tid]; sm[SMACT+tid]=0.f; sm[SSQ+tid]=0.f; }
    sm[PB1+tid]=b1[tid]; sm[PB1+tid+128]=b1[tid+128];
    sm[PB2+tid]=b2[tid]; sm[PB2+tid+128]=b2[tid+128];
    sm[PW3+tid]=w3[tid]; sm[PW3+tid+128]=w3[tid+128];
    if (tid == 0) sm[PB3]=b3[0];
    {
        const float4* x4 = (const float4*)(x + r0*128);
        const float4* m4 = (const float4*)(m + r0*128);
        #pragma unroll 4
        for (int i = 0; i < 8; i++) {
            int q = tid + i*128, row = q >> 5, c4 = q & 31;
            float4 v = x4[q];
            v.x=rt(v.x); v.y=rt(v.y); v.z=rt(v.z); v.w=rt(v.w);
            *(float4*)&sm[XMF + row*260 + c4*4] = v;
            float4 u = m4[q];
            u.x=rt(tanhf(u.x)); u.y=rt(tanhf(u.y)); u.z=rt(tanhf(u.z)); u.w=rt(tanhf(u.w));
            *(float4*)&sm[XMF + row*260 + 128 + c4*4] = u;
        }
        const float4* s1 = (const float4*)(g_wr + GF1);
        #pragma unroll 4
        for (int i = 0; i < 16; i++) {
            int q = tid + i*128, row = q >> 5, c4 = q & 31;
            *(float4*)&sm[F1W + row*132 + c4*4] = s1[q];
        }
    }
    __syncthreads();

    // ---------------- P1: fc1 [32x64], K=128; keep v=D+bias in regs; ssq via shfl+atomics ----
    const int rb1 = (wid >> 1) * 16, nb1 = (wid & 1) * 32;
    float ac1[4][4] = {};
    mt<16,4,260,132>(ac1, sm + XMF + rb1*260, sm + F1W + nb1*132);
    {
        float p0 = 0.f, p1 = 0.f;
        #pragma unroll
        for (int n = 0; n < 4; n++) {
            int cb = nb1 + n*8 + 2*l4;
            ac1[n][0] += sm[PF1B+cb];   ac1[n][1] += sm[PF1B+cb+1];
            ac1[n][2] += sm[PF1B+cb];   ac1[n][3] += sm[PF1B+cb+1];
            p0 += ac1[n][0]*ac1[n][0] + ac1[n][1]*ac1[n][1];
            p1 += ac1[n][2]*ac1[n][2] + ac1[n][3]*ac1[n][3];
        }
        p0 += __shfl_xor_sync(~0u, p0, 1); p0 += __shfl_xor_sync(~0u, p0, 2);
        p1 += __shfl_xor_sync(~0u, p1, 1); p1 += __shfl_xor_sync(~0u, p1, 2);
        if (l4 == 0) {
            atomicAdd(&sm[SSQ + rb1 + g],     p0);
            atomicAdd(&sm[SSQ + rb1 + 8 + g], p1);
        }
    }
    __syncthreads();

    // ---------------- P2: z = rt(tanh(v*inv)) -> ZB ; tanh(x) in place ; load F2W,F3W ----
    {
        float inv0 = 1.0f / fmaxf(sqrtf(sm[SSQ + rb1 + g]),     1e-12f);
        float inv1 = 1.0f / fmaxf(sqrtf(sm[SSQ + rb1 + 8 + g]), 1e-12f);
        #pragma unroll
        for (int n = 0; n < 4; n++) {
            int cb = nb1 + n*8 + 2*l4;
            sm[ZB + (rb1+g)*68 + cb]     = rt(tanhf(ac1[n][0]*inv0));
            sm[ZB + (rb1+g)*68 + cb+1]   = rt(tanhf(ac1[n][1]*inv0));
            sm[ZB + (rb1+8+g)*68 + cb]   = rt(tanhf(ac1[n][2]*inv1));
            sm[ZB + (rb1+8+g)*68 + cb+1] = rt(tanhf(ac1[n][3]*inv1));
        }
        #pragma unroll 4
        for (int i = 0; i < 8; i++) {
            int q = tid + i*128, r = q >> 5, c4 = q & 31;
            float4* p = (float4*)&sm[XMF + r*260 + c4*4];
            float4 v = *p;
            v.x=rt(tanhf(v.x)); v.y=rt(tanhf(v.y)); v.z=rt(tanhf(v.z)); v.w=rt(tanhf(v.w));
            *p = v;
        }
        const float4* s2 = (const float4*)(g_wr + GF2);
        for (int q = tid; q < 3072; q += 128) {
            int row = q / 48, c4 = q - row*48;
            *(float4*)&sm[F2W + row*196 + c4*4] = s2[q];
        }
        const float4* s3 = (const float4*)(g_wr + GF3);
        for (int q = tid; q < 512; q += 128) {
            int row = q >> 4, c4 = q & 15;
            *(float4*)&sm[F3W + row*68 + c4*4] = s3[q];
        }
    }
    __syncthreads();

    // ---------------- P3: fc2 [32x64], K=192 = [z | tanh(m)] ----------------
    float ac2[4][4] = {};
    mt<8,4,68,196>(ac2, sm + ZB + rb1*68, sm + F2W + nb1*196);
    mt<16,4,260,196>(ac2, sm + XMF + rb1*260 + 128, sm + F2W + nb1*196 + 64);
    __syncthreads();   // z dead; ZB reused for z2
    #pragma unroll
    for (int n = 0; n < 4; n++) {
        int cb = nb1 + n*8 + 2*l4;
        sm[ZB + (rb1+g)*68 + cb]     = rt(tanhf(ac2[n][0] + sm[PF2B+cb]));
        sm[ZB + (rb1+g)*68 + cb+1]   = rt(tanhf(ac2[n][1] + sm[PF2B+cb+1]));
        sm[ZB + (rb1+8+g)*68 + cb]   = rt(tanhf(ac2[n][2] + sm[PF2B+cb]));
        sm[ZB + (rb1+8+g)*68 + cb+1] = rt(tanhf(ac2[n][3] + sm[PF2B+cb+1]));
    }
    __syncthreads();

    // ---------------- P4: fc3 (warps 0-1) || prefetch W1 q0 (warps 2-3) ----------------
    if (wid < 2) {
        const int rb = wid * 16;
        float ac[4][4] = {};
        mt<8,4,68,68>(ac, sm + ZB + rb*68, sm + F3W);
        #pragma unroll
        for (int n = 0; n < 4; n++) {
            int cb = n*8 + 2*l4, r = rb + g;
            sm[MSGR + r*36 + cb]       = ac[n][0] + sm[PF3B+cb];
            sm[MSGR + r*36 + cb+1]     = ac[n][1] + sm[PF3B+cb+1];
            sm[MSGR + (r+8)*36 + cb]   = ac[n][2] + sm[PF3B+cb];
            sm[MSGR + (r+8)*36 + cb+1] = ac[n][3] + sm[PF3B+cb+1];
        }
    } else {
        ldq(sbu + BUF(wid,0)*4, wsl1, lane);
    }
    __syncthreads();

    // ---------------- P5: msg l2norm -> out (warps 2-3) || prefetch W1 q0 (warps 0-1) ----
    if (tid >= 64) {
        int t = tid - 64, row = t >> 1, sg = t & 1;
        float4 q0 = *(float4*)&sm[MSGR + row*36 + sg*16];
        float4 q1 = *(float4*)&sm[MSGR + row*36 + sg*16 + 4];
        float4 q2 = *(float4*)&sm[MSGR + row*36 + sg*16 + 8];
        float4 q3 = *(float4*)&sm[MSGR + row*36 + sg*16 + 12];
        float ss = q0.x*q0.x+q0.y*q0.y+q0.z*q0.z+q0.w*q0.w
                 + q1.x*q1.x+q1.y*q1.y+q1.z*q1.z+q1.w*q1.w
                 + q2.x*q2.x+q2.y*q2.y+q2.z*q2.z+q2.w*q2.w
                 + q3.x*q3.x+q3.y*q3.y+q3.z*q3.z+q3.w*q3.w;
        ss += __shfl_xor_sync(~0u, ss, 1);
        float inv = 1.0f / fmaxf(sqrtf(ss), 1e-12f);
        float4* og = (float4*)(out + (r0 + row)*32 + sg*16);
        og[0] = make_float4(q0.x*inv, q0.y*inv, q0.z*inv, q0.w*inv);
        og[1] = make_float4(q1.x*inv, q1.y*inv, q1.z*inv, q1.w*inv);
        og[2] = make_float4(q2.x*inv, q2.y*inv, q2.z*inv, q2.w*inv);
        og[3] = make_float4(q3.x*inv, q3.y*inv, q3.z*inv, q3.w*inv);
    } else {
        ldq(sbu + BUF(wid,0)*4, wsl1, lane);
    }
    __syncthreads();

    // ---------------- action L1: h1 in regs, per-warp k32 double-buffered pipeline ----
    const int nb = wid * 64;
    float h1a[2][8][4];
    #pragma unroll
    for (int s = 0; s < 2; s++)
        #pragma unroll
        for (int t = 0; t < 8; t++)
            h1a[s][t][0]=h1a[s][t][1]=h1a[s][t][2]=h1a[s][t][3]=0.f;
    #pragma unroll
    for (int q = 0; q < 8; q++) {
        const float* nsrc = (q < 7) ? (wsl1 + (q+1)*32) : wsl2;
        ldq(sbu + BUF(wid,(q+1)&1)*4, nsrc, lane);
        CPWAIT1();
        mma32x64(h1a, sm + XMF + q*32, sm + BUF(wid, q&1));
    }
    __syncthreads();
    #pragma unroll
    for (int s = 0; s < 2; s++)
        #pragma unroll
        for (int t = 0; t < 8; t++) {
            int cb = nb + t*8 + 2*l4, r = s*16 + g;
            float ba = sm[PB1+cb], bb = sm[PB1+cb+1];
            *(float2*)&sm[XMF + r*260 + cb] =
                make_float2(rt(fmaxf(h1a[s][t][0]+ba,0.f)), rt(fmaxf(h1a[s][t][1]+bb,0.f)));
            *(float2*)&sm[XMF + (r+8)*260 + cb] =
                make_float2(rt(fmaxf(h1a[s][t][2]+ba,0.f)), rt(fmaxf(h1a[s][t][3]+bb,0.f)));
        }
    __syncthreads();

    // ---------------- action L2: fused w3 dot, h2 never stored ----------------
    float acl[2][8][4];
    #pragma unroll
    for (int s = 0; s < 2; s++)
        #pragma unroll
        for (int t = 0; t < 8; t++)
            acl[s][t][0]=acl[s][t][1]=acl[s][t][2]=acl[s][t][3]=0.f;
    #pragma unroll
    for (int q = 0; q < 8; q++) {
        if (q < 7) { ldq(sbu + BUF(wid,(q+1)&1)*4, wsl2 + (q+1)*32, lane); CPWAIT1(); }
        else       { CPWAIT0(); }
        mma32x64(acl, sm + XMF + q*32, sm + BUF(wid, q&1));
    }
    float pr[4] = {0,0,0,0};
    #pragma unroll
    for (int s = 0; s < 2; s++)
        #pragma unroll
        for (int t = 0; t < 8; t++) {
            int cb = nb + t*8 + 2*l4;
            float ba = sm[PB2+cb], bb = sm[PB2+cb+1];
            float wa = sm[PW3+cb], wb = sm[PW3+cb+1];
            pr[2*s]   += fmaxf(acl[s][t][0]+ba,0.f)*wa + fmaxf(acl[s][t][1]+bb,0.f)*wb;
            pr[2*s+1] += fmaxf(acl[s][t][2]+ba,0.f)*wa + fmaxf(acl[s][t][3]+bb,0.f)*wb;
        }
    #pragma unroll
    for (int i = 0; i < 4; i++) {
        pr[i] += __shfl_xor_sync(~0u, pr[i], 1);
        pr[i] += __shfl_xor_sync(~0u, pr[i], 2);
    }
    if (l4 == 0) {
        #pragma unroll
        for (int s = 0; s < 2; s++) {
            atomicAdd(&sm[SMACT + s*16 + g],     pr[2*s]);
            atomicAdd(&sm[SMACT + s*16 + 8 + g], pr[2*s+1]);
        }
    }
    __syncthreads();
    if (tid < 32)
        out[(long)Bn*32 + r0 + tid] = tanhf(sm[SMACT+tid] + sm[PB3]);
}

extern "C" void kernel_launch(void* const* d_in, const int* in_sizes, int n_in,
                              void* d_out, int out_size) {
    const float* x   = (const float*)d_in[0];
    const float* m   = (const float*)d_in[1];
    const float* f1w = (const float*)d_in[2];
    const float* f1b = (const float*)d_in[3];
    const float* f2w = (const float*)d_in[4];
    const float* f2b = (const float*)d_in[5];
    const float* f3w = (const float*)d_in[6];
    const float* f3b = (const float*)d_in[7];
    const float* w1  = (const float*)d_in[8];
    const float* b1  = (const float*)d_in[9];
    const float* w2  = (const float*)d_in[10];
    const float* b2  = (const float*)d_in[11];
    const float* w3  = (const float*)d_in[12];
    const float* b3  = (const float*)d_in[13];
    float* out = (float*)d_out;

    int Bn = in_sizes[0] / 128;
    prep_weights<<<128, 256>>>(f1w, f2w, f3w, w1, w2);
    cudaFuncSetAttribute(actor_kernel, cudaFuncAttributeMaxDynamicSharedMemorySize, SMEMB);
    actor_kernel<<<Bn / 32, 128, SMEMB>>>(x, m, f1b, f2b, f3b,
                                          b1, b2, w3, b3, out, Bn);
}

// round 16
// speedup vs baseline: 1.0023x; 1.0023x over previous
#include <cuda_runtime.h>
#include <cstdint>

// ---------------- smem float offsets (32-row tile, 128 threads) ----------------
#define XMF 0                    // 32 x 260 plane: tanh-staged x | tanh(m), later h1
#define RB  8320                 // region: action buffers / msg overlays (18432 floats)
#define BUF(w,s) (RB + ((s)*4+(w))*2304)   // 8 buffers of 64x36
#define F1W  RB                  // 64x132, live P0->P1
#define F2W  RB                  // 64x196, live P2->P3 (after F1W dead)
#define F3W  (RB+12544)          // 32x68,  live P2->P4
#define ZB   (RB+14720)          // 32x68: z (P2->P3), then z2 (P3->P4)
#define MSGR (RB+9216)           // 32x36, live P4->P5 (warp0 slot1, written later)
#define PF1B 26752
#define PF2B 26816
#define PF3B 26880
#define PB1  26912
#define PB2  27168
#define PW3  27424
#define PB3  27680
#define SMACT 27684
#define SSQ  27716
#define SMEMF 27748
#define SMEMB (SMEMF*4)

// pre-rounded (tf32-rna) weights in device scratch
#define GF1 0
#define GF2 8192
#define GF3 20480
#define GW1 22528
#define GW2 88064
__device__ __align__(16) float g_wr[153600];

__device__ __forceinline__ float rt(float x){
    uint32_t u; asm("cvt.rna.tf32.f32 %0, %1;" : "=r"(u) : "f"(x));
    return __uint_as_float(u);
}
__device__ __forceinline__ uint32_t smem_u32(const void* p){
    uint32_t a;
    asm("{ .reg .u64 t; cvta.to.shared.u64 t, %1; cvt.u32.u64 %0, t; }" : "=r"(a) : "l"(p));
    return a;
}
__device__ __forceinline__ void mma8(float* d, uint32_t a0,uint32_t a1,uint32_t a2,uint32_t a3,
                                     uint32_t b0,uint32_t b1){
    asm("mma.sync.aligned.m16n8k8.row.col.f32.tf32.tf32.f32 "
        "{%0,%1,%2,%3},{%4,%5,%6,%7},{%8,%9},{%0,%1,%2,%3};"
        : "+f"(d[0]),"+f"(d[1]),"+f"(d[2]),"+f"(d[3])
        : "r"(a0),"r"(a1),"r"(a2),"r"(a3),"r"(b0),"r"(b1));
}
// msg tile: m16 x (NS*8), K=KS*8, strides AS/WS (% 32 == 4 -> conflict-free)
template<int KS,int NS,int AS,int WS>
__device__ __forceinline__ void mt(float (&acc)[4][4], const float* A, const float* W){
    const int lane = threadIdx.x & 31, g = lane >> 2, l4 = lane & 3;
    const uint32_t* a = (const uint32_t*)(A + g*AS + l4);
    const uint32_t* w = (const uint32_t*)(W + g*WS + l4);
    #pragma unroll 8
    for (int k = 0; k < KS; k++) {
        uint32_t a0=a[0], a1=a[8*AS], a2=a[4], a3=a[8*AS+4];
        #pragma unroll
        for (int n = 0; n < NS; n++)
            mma8(acc[n], a0,a1,a2,a3, w[n*8*WS], w[n*8*WS+4]);
        a += 8; w += 8;
    }
}
// action tile: m32 x n64, one k32 chunk. A stride 260 (XM), W stride 36.
__device__ __forceinline__ void mma32x64(float (&acc)[2][8][4], const float* A, const float* W){
    const int lane = threadIdx.x & 31, g = lane >> 2, l4 = lane & 3;
    const uint32_t* a = (const uint32_t*)(A + g*260 + l4);
    const uint32_t* w = (const uint32_t*)(W + g*36 + l4);
    #pragma unroll
    for (int k = 0; k < 4; k++) {
        uint32_t av[2][4];
        #pragma unroll
        for (int s = 0; s < 2; s++) {
            av[s][0]=a[s*16*260];   av[s][1]=a[(s*16+8)*260];
            av[s][2]=a[s*16*260+4]; av[s][3]=a[(s*16+8)*260+4];
        }
        #pragma unroll
        for (int t = 0; t < 8; t++) {
            uint32_t b0 = w[t*8*36], b1 = w[t*8*36+4];
            #pragma unroll
            for (int s = 0; s < 2; s++)
                mma8(acc[s][t], av[s][0],av[s][1],av[s][2],av[s][3], b0,b1);
        }
        a += 8; w += 8;
    }
}
// one warp streams a 64(n) x 32(k) chunk (gmem row stride 256) into a 64x36 buffer
__device__ __forceinline__ void ldq(uint32_t sdst, const float* g, int lane){
    #pragma unroll
    for (int i = 0; i < 16; i++) {
        int idx = lane + i*32;
        int row = idx >> 3, seg = idx & 7;
        uint32_t d = sdst + (uint32_t)(row*36 + seg*4)*4u;
        asm volatile("cp.async.cg.shared.global [%0], [%1], 16;"
                     :: "r"(d), "l"(g + row*256 + seg*4));
    }
    asm volatile("cp.async.commit_group;" ::: "memory");
}
#define CPWAIT1() asm volatile("cp.async.wait_group 1;" ::: "memory")
#define CPWAIT0() asm volatile("cp.async.wait_group 0;" ::: "memory")

__global__ void prep_weights(const float* f1w, const float* f2w, const float* f3w,
                             const float* w1, const float* w2){
    int i = blockIdx.x*blockDim.x + threadIdx.x, n = gridDim.x*blockDim.x;
    for (int k=i; k<8192;  k+=n) g_wr[GF1+k] = rt(f1w[k]);
    for (int k=i; k<12288; k+=n) g_wr[GF2+k] = rt(f2w[k]);
    for (int k=i; k<2048;  k+=n) g_wr[GF3+k] = rt(f3w[k]);
    for (int k=i; k<65536; k+=n) g_wr[GW1+k] = rt(w1[k]);
    for (int k=i; k<65536; k+=n) g_wr[GW2+k] = rt(w2[k]);
}

__global__ void __launch_bounds__(128, 2)
actor_kernel(const float* __restrict__ x,  const float* __restrict__ m,
             const float* __restrict__ f1b, const float* __restrict__ f2b,
             const float* __restrict__ f3b,
             const float* __restrict__ b1,  const float* __restrict__ b2,
             const float* __restrict__ w3,  const float* __restrict__ b3,
             float* __restrict__ out, int Bn)
{
    extern __shared__ float sm[];
    const uint32_t sbu = smem_u32(sm);
    const int tid = threadIdx.x, wid = tid >> 5, lane = tid & 31;
    const int g = lane >> 2, l4 = lane & 3;
    const long r0 = (long)blockIdx.x * 32;
    const float* wsl1 = g_wr + GW1 + wid*16384;   // this warp's W1 rows [wid*64, +64)
    const float* wsl2 = g_wr + GW2 + wid*16384;

    // ---------------- P0: params + inputs + f1w ----------------
    if (tid < 64) { sm[PF1B+tid]=f1b[tid]; sm[PF2B+tid]=f2b[tid]; }
    if (tid < 32) { sm[PF3B+tid]=f3b[tid]; sm[SMACT+tid]=0.f; sm[SSQ+tid]=0.f; }
    sm[PB1+tid]=b1[tid]; sm[PB1+tid+128]=b1[tid+128];
    sm[PB2+tid]=b2[tid]; sm[PB2+tid+128]=b2[tid+128];
    sm[PW3+tid]=w3[tid]; sm[PW3+tid+128]=w3[tid+128];
    if (tid == 0) sm[PB3]=b3[0];
    {
        const float4* x4 = (const float4*)(x + r0*128);
        const float4* m4 = (const float4*)(m + r0*128);
        #pragma unroll 4
        for (int i = 0; i < 8; i++) {
            int q = tid + i*128, row = q >> 5, c4 = q & 31;
            float4 v = x4[q];
            v.x=rt(v.x); v.y=rt(v.y); v.z=rt(v.z); v.w=rt(v.w);
            *(float4*)&sm[XMF + row*260 + c4*4] = v;
            float4 u = m4[q];
            u.x=rt(tanhf(u.x)); u.y=rt(tanhf(u.y)); u.z=rt(tanhf(u.z)); u.w=rt(tanhf(u.w));
            *(float4*)&sm[XMF + row*260 + 128 + c4*4] = u;
        }
        const float4* s1 = (const float4*)(g_wr + GF1);
        #pragma unroll 4
        for (int i = 0; i < 16; i++) {
            int q = tid + i*128, row = q >> 5, c4 = q & 31;
            *(float4*)&sm[F1W + row*132 + c4*4] = s1[q];
        }
    }
    __syncthreads();

    // ---------------- P1: fc1 [32x64], K=128; keep v=D+bias in regs; ssq via shfl+atomics ----
    const int rb1 = (wid >> 1) * 16, nb1 = (wid & 1) * 32;
    float ac1[4][4] = {};
    mt<16,4,260,132>(ac1, sm + XMF + rb1*260, sm + F1W + nb1*132);
    {
        float p0 = 0.f, p1 = 0.f;
        #pragma unroll
        for (int n = 0; n < 4; n++) {
            int cb = nb1 + n*8 + 2*l4;
            ac1[n][0] += sm[PF1B+cb];   ac1[n][1] += sm[PF1B+cb+1];
            ac1[n][2] += sm[PF1B+cb];   ac1[n][3] += sm[PF1B+cb+1];
            p0 += ac1[n][0]*ac1[n][0] + ac1[n][1]*ac1[n][1];
            p1 += ac1[n][2]*ac1[n][2] + ac1[n][3]*ac1[n][3];
        }
        p0 += __shfl_xor_sync(~0u, p0, 1); p0 += __shfl_xor_sync(~0u, p0, 2);
        p1 += __shfl_xor_sync(~0u, p1, 1); p1 += __shfl_xor_sync(~0u, p1, 2);
        if (l4 == 0) {
            atomicAdd(&sm[SSQ + rb1 + g],     p0);
            atomicAdd(&sm[SSQ + rb1 + 8 + g], p1);
        }
    }
    __syncthreads();

    // ---------------- P2: z = rt(tanh(v*inv)) -> ZB ; tanh(x) in place ; load F2W,F3W ----
    {
        float inv0 = 1.0f / fmaxf(sqrtf(sm[SSQ + rb1 + g]),     1e-12f);
        float inv1 = 1.0f / fmaxf(sqrtf(sm[SSQ + rb1 + 8 + g]), 1e-12f);
        #pragma unroll
        for (int n = 0; n < 4; n++) {
            int cb = nb1 + n*8 + 2*l4;
            sm[ZB + (rb1+g)*68 + cb]     = rt(tanhf(ac1[n][0]*inv0));
            sm[ZB + (rb1+g)*68 + cb+1]   = rt(tanhf(ac1[n][1]*inv0));
            sm[ZB + (rb1+8+g)*68 + cb]   = rt(tanhf(ac1[n][2]*inv1));
            sm[ZB + (rb1+8+g)*68 + cb+1] = rt(tanhf(ac1[n][3]*inv1));
        }
        #pragma unroll 4
        for (int i = 0; i < 8; i++) {
            int q = tid + i*128, r = q >> 5, c4 = q & 31;
            float4* p = (float4*)&sm[XMF + r*260 + c4*4];
            float4 v = *p;
            v.x=rt(tanhf(v.x)); v.y=rt(tanhf(v.y)); v.z=rt(tanhf(v.z)); v.w=rt(tanhf(v.w));
            *p = v;
        }
        const float4* s2 = (const float4*)(g_wr + GF2);
        for (int q = tid; q < 3072; q += 128) {
            int row = q / 48, c4 = q - row*48;
            *(float4*)&sm[F2W + row*196 + c4*4] = s2[q];
        }
        const float4* s3 = (const float4*)(g_wr + GF3);
        for (int q = tid; q < 512; q += 128) {
            int row = q >> 4, c4 = q & 15;
            *(float4*)&sm[F3W + row*68 + c4*4] = s3[q];
        }
    }
    __syncthreads();

    // ---------------- P3: fc2 [32x64], K=192 = [z | tanh(m)] ----------------
    float ac2[4][4] = {};
    mt<8,4,68,196>(ac2, sm + ZB + rb1*68, sm + F2W + nb1*196);
    mt<16,4,260,196>(ac2, sm + XMF + rb1*260 + 128, sm + F2W + nb1*196 + 64);
    __syncthreads();   // z dead; ZB reused for z2
    #pragma unroll
    for (int n = 0; n < 4; n++) {
        int cb = nb1 + n*8 + 2*l4;
        sm[ZB + (rb1+g)*68 + cb]     = rt(tanhf(ac2[n][0] + sm[PF2B+cb]));
        sm[ZB + (rb1+g)*68 + cb+1]   = rt(tanhf(ac2[n][1] + sm[PF2B+cb+1]));
        sm[ZB + (rb1+8+g)*68 + cb]   = rt(tanhf(ac2[n][2] + sm[PF2B+cb]));
        sm[ZB + (rb1+8+g)*68 + cb+1] = rt(tanhf(ac2[n][3] + sm[PF2B+cb+1]));
    }
    __syncthreads();

    // ---------------- P4: fc3 (warps 0-1) || prefetch W1 q0 (warps 2-3) ----------------
    if (wid < 2) {
        const int rb = wid * 16;
        float ac[4][4] = {};
        mt<8,4,68,68>(ac, sm + ZB + rb*68, sm + F3W);
        #pragma unroll
        for (int n = 0; n < 4; n++) {
            int cb = n*8 + 2*l4, r = rb + g;
            sm[MSGR + r*36 + cb]       = ac[n][0] + sm[PF3B+cb];
            sm[MSGR + r*36 + cb+1]     = ac[n][1] + sm[PF3B+cb+1];
            sm[MSGR + (r+8)*36 + cb]   = ac[n][2] + sm[PF3B+cb];
            sm[MSGR + (r+8)*36 + cb+1] = ac[n][3] + sm[PF3B+cb+1];
        }
    } else {
        ldq(sbu + BUF(wid,0)*4, wsl1, lane);
    }
    __syncthreads();

    // ---------------- P5: msg l2norm -> out (warps 2-3) || prefetch W1 q0 (warps 0-1) ----
    if (tid >= 64) {
        int t = tid - 64, row = t >> 1, sg = t & 1;
        float4 q0 = *(float4*)&sm[MSGR + row*36 + sg*16];
        float4 q1 = *(float4*)&sm[MSGR + row*36 + sg*16 + 4];
        float4 q2 = *(float4*)&sm[MSGR + row*36 + sg*16 + 8];
        float4 q3 = *(float4*)&sm[MSGR + row*36 + sg*16 + 12];
        float ss = q0.x*q0.x+q0.y*q0.y+q0.z*q0.z+q0.w*q0.w
                 + q1.x*q1.x+q1.y*q1.y+q1.z*q1.z+q1.w*q1.w
                 + q2.x*q2.x+q2.y*q2.y+q2.z*q2.z+q2.w*q2.w
                 + q3.x*q3.x+q3.y*q3.y+q3.z*q3.z+q3.w*q3.w;
        ss += __shfl_xor_sync(~0u, ss, 1);
        float inv = 1.0f / fmaxf(sqrtf(ss), 1e-12f);
        float4* og = (float4*)(out + (r0 + row)*32 + sg*16);
        og[0] = make_float4(q0.x*inv, q0.y*inv, q0.z*inv, q0.w*inv);
        og[1] = make_float4(q1.x*inv, q1.y*inv, q1.z*inv, q1.w*inv);
        og[2] = make_float4(q2.x*inv, q2.y*inv, q2.z*inv, q2.w*inv);
        og[3] = make_float4(q3.x*inv, q3.y*inv, q3.z*inv, q3.w*inv);
    } else {
        ldq(sbu + BUF(wid,0)*4, wsl1, lane);
    }
    __syncthreads();

    // ---------------- action L1: h1 in regs, per-warp k32 double-buffered pipeline ----
    const int nb = wid * 64;
    float h1a[2][8][4];
    #pragma unroll
    for (int s = 0; s < 2; s++)
        #pragma unroll
        for (int t = 0; t < 8; t++)
            h1a[s][t][0]=h1a[s][t][1]=h1a[s][t][2]=h1a[s][t][3]=0.f;
    #pragma unroll
    for (int q = 0; q < 8; q++) {
        const float* nsrc = (q < 7) ? (wsl1 + (q+1)*32) : wsl2;
        ldq(sbu + BUF(wid,(q+1)&1)*4, nsrc, lane);
        CPWAIT1();
        mma32x64(h1a, sm + XMF + q*32, sm + BUF(wid, q&1));
    }
    __syncthreads();
    #pragma unroll
    for (int s = 0; s < 2; s++)
        #pragma unroll
        for (int t = 0; t < 8; t++) {
            int cb = nb + t*8 + 2*l4, r = s*16 + g;
            float ba = sm[PB1+cb], bb = sm[PB1+cb+1];
            *(float2*)&sm[XMF + r*260 + cb] =
                make_float2(rt(fmaxf(h1a[s][t][0]+ba,0.f)), rt(fmaxf(h1a[s][t][1]+bb,0.f)));
            *(float2*)&sm[XMF + (r+8)*260 + cb] =
                make_float2(rt(fmaxf(h1a[s][t][2]+ba,0.f)), rt(fmaxf(h1a[s][t][3]+bb,0.f)));
        }
    __syncthreads();

    // ---------------- action L2: fused w3 dot, h2 never stored ----------------
    float acl[2][8][4];
    #pragma unroll
    for (int s = 0; s < 2; s++)
        #pragma unroll
        for (int t = 0; t < 8; t++)
            acl[s][t][0]=acl[s][t][1]=acl[s][t][2]=acl[s][t][3]=0.f;
    #pragma unroll
    for (int q = 0; q < 8; q++) {
        if (q < 7) { ldq(sbu + BUF(wid,(q+1)&1)*4, wsl2 + (q+1)*32, lane); CPWAIT1(); }
        else       { CPWAIT0(); }
        mma32x64(acl, sm + XMF + q*32, sm + BUF(wid, q&1));
    }
    float pr[4] = {0,0,0,0};
    #pragma unroll
    for (int s = 0; s < 2; s++)
        #pragma unroll
        for (int t = 0; t < 8; t++) {
            int cb = nb + t*8 + 2*l4;
            float ba = sm[PB2+cb], bb = sm[PB2+cb+1];
            float wa = sm[PW3+cb], wb = sm[PW3+cb+1];
            pr[2*s]   += fmaxf(acl[s][t][0]+ba,0.f)*wa + fmaxf(acl[s][t][1]+bb,0.f)*wb;
            pr[2*s+1] += fmaxf(acl[s][t][2]+ba,0.f)*wa + fmaxf(acl[s][t][3]+bb,0.f)*wb;
        }
    #pragma unroll
    for (int i = 0; i < 4; i++) {
        pr[i] += __shfl_xor_sync(~0u, pr[i], 1);
        pr[i] += __shfl_xor_sync(~0u, pr[i], 2);
    }
    if (l4 == 0) {
        #pragma unroll
        for (int s = 0; s < 2; s++) {
            atomicAdd(&sm[SMACT + s*16 + g],     pr[2*s]);
            atomicAdd(&sm[SMACT + s*16 + 8 + g], pr[2*s+1]);
        }
    }
    __syncthreads();
    if (tid < 32)
        out[(long)Bn*32 + r0 + tid] = tanhf(sm[SMACT+tid] + sm[PB3]);
}

extern "C" void kernel_launch(void* const* d_in, const int* in_sizes, int n_in,
                              void* d_out, int out_size) {
    const float* x   = (const float*)d_in[0];
    const float* m   = (const float*)d_in[1];
    const float* f1w = (const float*)d_in[2];
    const float* f1b = (const float*)d_in[3];
    const float* f2w = (const float*)d_in[4];
    const float* f2b = (const float*)d_in[5];
    const float* f3w = (const float*)d_in[6];
    const float* f3b = (const float*)d_in[7];
    const float* w1  = (const float*)d_in[8];
    const float* b1  = (const float*)d_in[9];
    const float* w2  = (const float*)d_in[10];
    const float* b2  = (const float*)d_in[11];
    const float* w3  = (const float*)d_in[12];
    const float* b3  = (const float*)d_in[13];
    float* out = (float*)d_out;

    int Bn = in_sizes[0] / 128;
    prep_weights<<<128, 256>>>(f1w, f2w, f3w, w1, w2);
    cudaFuncSetAttribute(actor_kernel, cudaFuncAttributeMaxDynamicSharedMemorySize, SMEMB);
    actor_kernel<<<Bn / 32, 128, SMEMB>>>(x, m, f1b, f2b, f3b,
                                          b1, b2, w3, b3, out, Bn);
}

// round 17
// speedup vs baseline: 1.1240x; 1.1215x over previous
#include <cuda_runtime.h>
#include <cstdint>

// ---------------- smem float offsets (128-row tile, 256 threads) ----------------
#define XMF 0                    // 128 x 260 plane: x|tanh(m), later h1
#define RB  33280                // chunk buffers / msg overlays
#define BUF(w,s) (RB + ((s)*8+(w))*1152)   // 16 buffers of 32x36 (k32 chunks), RB..RB+18432
#define F1W  RB                  // 64x132, live P0->P1
#define F2W  RB                  // 64x196, live P2->P3
#define ZB   (RB+12544)          // 128x68: z (P2->P3), then z2 (P3->P4)
#define F3W  (RB+21248)          // 32x68, live P2->P4
#define MSGR (RB+18816)          // 128x36, live P4->P5 (over dead ZB tail/F3W)
#define PF1B 56704
#define PF2B 56768
#define PF3B 56832
#define PB1  56864
#define PB2  57120
#define PW3  57376
#define PB3  57632
#define SMACT 57636
#define SSQ  57764
#define SMEMF 57892
#define SMEMB (SMEMF*4)          // 231,568 B <= 227KB opt-in

// pre-rounded (tf32-rna) weights in device scratch
#define GF1 0
#define GF2 8192
#define GF3 20480
#define GW1 22528
#define GW2 88064
__device__ __align__(16) float g_wr[153600];

__device__ __forceinline__ float rt(float x){
    uint32_t u; asm("cvt.rna.tf32.f32 %0, %1;" : "=r"(u) : "f"(x));
    return __uint_as_float(u);
}
__device__ __forceinline__ uint32_t smem_u32(const void* p){
    uint32_t a;
    asm("{ .reg .u64 t; cvta.to.shared.u64 t, %1; cvt.u32.u64 %0, t; }" : "=r"(a) : "l"(p));
    return a;
}
__device__ __forceinline__ void mma8(float* d, uint32_t a0,uint32_t a1,uint32_t a2,uint32_t a3,
                                     uint32_t b0,uint32_t b1){
    asm("mma.sync.aligned.m16n8k8.row.col.f32.tf32.tf32.f32 "
        "{%0,%1,%2,%3},{%4,%5,%6,%7},{%8,%9},{%0,%1,%2,%3};"
        : "+f"(d[0]),"+f"(d[1]),"+f"(d[2]),"+f"(d[3])
        : "r"(a0),"r"(a1),"r"(a2),"r"(a3),"r"(b0),"r"(b1));
}
// msg tile: m16 x (NS*8), K=KS*8, strides AS/WS (% 32 == 4 -> conflict-free)
template<int KS,int NS,int AS,int WS>
__device__ __forceinline__ void mt(float (&acc)[4][4], const float* A, const float* W){
    const int lane = threadIdx.x & 31, g = lane >> 2, l4 = lane & 3;
    const uint32_t* a = (const uint32_t*)(A + g*AS + l4);
    const uint32_t* w = (const uint32_t*)(W + g*WS + l4);
    #pragma unroll 8
    for (int k = 0; k < KS; k++) {
        uint32_t a0=a[0], a1=a[8*AS], a2=a[4], a3=a[8*AS+4];
        #pragma unroll
        for (int n = 0; n < NS; n++)
            mma8(acc[n], a0,a1,a2,a3, w[n*8*WS], w[n*8*WS+4]);
        a += 8; w += 8;
    }
}
// action tile: m128 x n32, one k32 chunk. A stride 260 (XM), W stride 36.
__device__ __forceinline__ void mma128(float (&acc)[8][4][4], const float* A, const float* W){
    const int lane = threadIdx.x & 31, g = lane >> 2, l4 = lane & 3;
    const uint32_t* a = (const uint32_t*)(A + g*260 + l4);
    const uint32_t* w = (const uint32_t*)(W + g*36 + l4);
    #pragma unroll
    for (int k = 0; k < 4; k++) {
        uint32_t av[8][4];
        #pragma unroll
        for (int s = 0; s < 8; s++) {
            av[s][0]=a[s*16*260];   av[s][1]=a[(s*16+8)*260];
            av[s][2]=a[s*16*260+4]; av[s][3]=a[(s*16+8)*260+4];
        }
        #pragma unroll
        for (int t = 0; t < 4; t++) {
            uint32_t b0 = w[t*8*36], b1 = w[t*8*36+4];
            #pragma unroll
            for (int s = 0; s < 8; s++)
                mma8(acc[s][t], av[s][0],av[s][1],av[s][2],av[s][3], b0,b1);
        }
        a += 8; w += 8;
    }
}
// one warp streams a 32(n) x 32(k) chunk (gmem row stride 256) into a 32x36 buffer
__device__ __forceinline__ void ldq(uint32_t sdst, const float* g, int lane){
    #pragma unroll
    for (int i = 0; i < 8; i++) {
        int idx = lane + i*32;
        int row = idx >> 3, seg = idx & 7;
        uint32_t d = sdst + (uint32_t)(row*36 + seg*4)*4u;
        asm volatile("cp.async.cg.shared.global [%0], [%1], 16;"
                     :: "r"(d), "l"(g + row*256 + seg*4));
    }
    asm volatile("cp.async.commit_group;" ::: "memory");
}
#define CPWAIT1() asm volatile("cp.async.wait_group 1;" ::: "memory")
#define CPWAIT0() asm volatile("cp.async.wait_group 0;" ::: "memory")

__global__ void prep_weights(const float* f1w, const float* f2w, const float* f3w,
                             const float* w1, const float* w2){
    int i = blockIdx.x*blockDim.x + threadIdx.x, n = gridDim.x*blockDim.x;
    for (int k=i; k<8192;  k+=n) g_wr[GF1+k] = rt(f1w[k]);
    for (int k=i; k<12288; k+=n) g_wr[GF2+k] = rt(f2w[k]);
    for (int k=i; k<2048;  k+=n) g_wr[GF3+k] = rt(f3w[k]);
    for (int k=i; k<65536; k+=n) g_wr[GW1+k] = rt(w1[k]);
    for (int k=i; k<65536; k+=n) g_wr[GW2+k] = rt(w2[k]);
}

__global__ void __launch_bounds__(256, 1)
actor_kernel(const float* __restrict__ x,  const float* __restrict__ m,
             const float* __restrict__ f1b, const float* __restrict__ f2b,
             const float* __restrict__ f3b,
             const float* __restrict__ b1,  const float* __restrict__ b2,
             const float* __restrict__ w3,  const float* __restrict__ b3,
             float* __restrict__ out, int Bn)
{
    extern __shared__ float sm[];
    const uint32_t sbu = smem_u32(sm);
    const int tid = threadIdx.x, wid = tid >> 5, lane = tid & 31;
    const int g = lane >> 2, l4 = lane & 3;
    const long r0 = (long)blockIdx.x * 128;
    const int nb = wid * 32;                      // this warp's action n-slice
    const float* wsl1 = g_wr + GW1 + nb*256;
    const float* wsl2 = g_wr + GW2 + nb*256;

    // ---------------- P0: params + inputs + f1w ----------------
    if (tid < 64) { sm[PF1B+tid]=f1b[tid]; sm[PF2B+tid]=f2b[tid]; }
    if (tid < 32) sm[PF3B+tid]=f3b[tid];
    if (tid < 128){ sm[SMACT+tid]=0.f; sm[SSQ+tid]=0.f; }
    sm[PB1+tid]=b1[tid]; sm[PB2+tid]=b2[tid]; sm[PW3+tid]=w3[tid];
    if (tid == 0) sm[PB3]=b3[0];
    {
        const float4* x4 = (const float4*)(x + r0*128);
        const float4* m4 = (const float4*)(m + r0*128);
        #pragma unroll 4
        for (int i = 0; i < 16; i++) {
            int q = tid + i*256, row = q >> 5, c4 = q & 31;
            float4 v = x4[q];
            v.x=rt(v.x); v.y=rt(v.y); v.z=rt(v.z); v.w=rt(v.w);
            *(float4*)&sm[XMF + row*260 + c4*4] = v;
            float4 u = m4[q];
            u.x=rt(tanhf(u.x)); u.y=rt(tanhf(u.y)); u.z=rt(tanhf(u.z)); u.w=rt(tanhf(u.w));
            *(float4*)&sm[XMF + row*260 + 128 + c4*4] = u;
        }
        const float4* s1 = (const float4*)(g_wr + GF1);
        #pragma unroll 4
        for (int i = 0; i < 8; i++) {
            int q = tid + i*256, row = q >> 5, c4 = q & 31;
            *(float4*)&sm[F1W + row*132 + c4*4] = s1[q];
        }
    }
    __syncthreads();

    // ---------------- P1: fc1 [128x64], K=128; v=D+bias in regs; ssq via shfl+atomics ----
    const int mg = wid >> 1, nb1 = (wid & 1) * 32;
    float ac1[2][4][4] = {};
    mt<16,4,260,132>(ac1[0], sm + XMF + (mg*32)*260,      sm + F1W + nb1*132);
    mt<16,4,260,132>(ac1[1], sm + XMF + (mg*32+16)*260,   sm + F1W + nb1*132);
    #pragma unroll
    for (int sub = 0; sub < 2; sub++) {
        int rb = mg*32 + sub*16;
        float p0 = 0.f, p1 = 0.f;
        #pragma unroll
        for (int n = 0; n < 4; n++) {
            int cb = nb1 + n*8 + 2*l4;
            ac1[sub][n][0] += sm[PF1B+cb];   ac1[sub][n][1] += sm[PF1B+cb+1];
            ac1[sub][n][2] += sm[PF1B+cb];   ac1[sub][n][3] += sm[PF1B+cb+1];
            p0 += ac1[sub][n][0]*ac1[sub][n][0] + ac1[sub][n][1]*ac1[sub][n][1];
            p1 += ac1[sub][n][2]*ac1[sub][n][2] + ac1[sub][n][3]*ac1[sub][n][3];
        }
        p0 += __shfl_xor_sync(~0u, p0, 1); p0 += __shfl_xor_sync(~0u, p0, 2);
        p1 += __shfl_xor_sync(~0u, p1, 1); p1 += __shfl_xor_sync(~0u, p1, 2);
        if (l4 == 0) {
            atomicAdd(&sm[SSQ + rb + g],     p0);
            atomicAdd(&sm[SSQ + rb + 8 + g], p1);
        }
    }
    __syncthreads();

    // ---------------- P2: z -> ZB ; tanh(x) in place ; load F2W + F3W ----------------
    #pragma unroll
    for (int sub = 0; sub < 2; sub++) {
        int rb = mg*32 + sub*16;
        float inv0 = 1.0f / fmaxf(sqrtf(sm[SSQ + rb + g]),     1e-12f);
        float inv1 = 1.0f / fmaxf(sqrtf(sm[SSQ + rb + 8 + g]), 1e-12f);
        #pragma unroll
        for (int n = 0; n < 4; n++) {
            int cb = nb1 + n*8 + 2*l4;
            sm[ZB + (rb+g)*68 + cb]     = rt(tanhf(ac1[sub][n][0]*inv0));
            sm[ZB + (rb+g)*68 + cb+1]   = rt(tanhf(ac1[sub][n][1]*inv0));
            sm[ZB + (rb+8+g)*68 + cb]   = rt(tanhf(ac1[sub][n][2]*inv1));
            sm[ZB + (rb+8+g)*68 + cb+1] = rt(tanhf(ac1[sub][n][3]*inv1));
        }
    }
    #pragma unroll 4
    for (int i = 0; i < 16; i++) {
        int q = tid + i*256, r = q >> 5, c4 = q & 31;
        float4* p = (float4*)&sm[XMF + r*260 + c4*4];
        float4 v = *p;
        v.x=rt(tanhf(v.x)); v.y=rt(tanhf(v.y)); v.z=rt(tanhf(v.z)); v.w=rt(tanhf(v.w));
        *p = v;
    }
    {
        const float4* s2 = (const float4*)(g_wr + GF2);
        for (int q = tid; q < 3072; q += 256) {
            int row = q / 48, c4 = q - row*48;
            *(float4*)&sm[F2W + row*196 + c4*4] = s2[q];
        }
        const float4* s3 = (const float4*)(g_wr + GF3);
        for (int q = tid; q < 512; q += 256) {
            int row = q >> 4, c4 = q & 15;
            *(float4*)&sm[F3W + row*68 + c4*4] = s3[q];
        }
    }
    __syncthreads();

    // ---------------- P3: fc2 [128x64], K=192 = [z | tanh(m)] ----------------
    float ac2[2][4][4] = {};
    #pragma unroll
    for (int sub = 0; sub < 2; sub++) {
        int rb = mg*32 + sub*16;
        mt<8,4,68,196>(ac2[sub], sm + ZB + rb*68, sm + F2W + nb1*196);
        mt<16,4,260,196>(ac2[sub], sm + XMF + rb*260 + 128, sm + F2W + nb1*196 + 64);
    }
    __syncthreads();   // z dead; ZB reused for z2
    #pragma unroll
    for (int sub = 0; sub < 2; sub++) {
        int rb = mg*32 + sub*16;
        #pragma unroll
        for (int n = 0; n < 4; n++) {
            int cb = nb1 + n*8 + 2*l4;
            sm[ZB + (rb+g)*68 + cb]     = rt(tanhf(ac2[sub][n][0] + sm[PF2B+cb]));
            sm[ZB + (rb+g)*68 + cb+1]   = rt(tanhf(ac2[sub][n][1] + sm[PF2B+cb+1]));
            sm[ZB + (rb+8+g)*68 + cb]   = rt(tanhf(ac2[sub][n][2] + sm[PF2B+cb]));
            sm[ZB + (rb+8+g)*68 + cb+1] = rt(tanhf(ac2[sub][n][3] + sm[PF2B+cb+1]));
        }
    }
    __syncthreads();

    // ---------------- P4: fc3 [128x32], K=64 (all 8 warps, m16n32) ----------------
    {
        const int rb3 = wid * 16;
        float ac3[4][4] = {};
        mt<8,4,68,68>(ac3, sm + ZB + rb3*68, sm + F3W);
        __syncthreads();            // all reads of z2/F3W done
        #pragma unroll
        for (int n = 0; n < 4; n++) {
            int cb = n*8 + 2*l4, r = rb3 + g;
            sm[MSGR + r*36 + cb]       = ac3[n][0] + sm[PF3B+cb];
            sm[MSGR + r*36 + cb+1]     = ac3[n][1] + sm[PF3B+cb+1];
            sm[MSGR + (r+8)*36 + cb]   = ac3[n][2] + sm[PF3B+cb];
            sm[MSGR + (r+8)*36 + cb+1] = ac3[n][3] + sm[PF3B+cb+1];
        }
        ldq(sbu + BUF(wid,0)*4, wsl1, lane);   // prefetch W1 chunk0 (slot s0: dead F2W)
    }
    __syncthreads();

    // ---------------- P5: msg l2norm -> out (all 256 threads, 2 per row) ----------------
    {
        int row = tid >> 1, sg = tid & 1;
        float4 q0 = *(float4*)&sm[MSGR + row*36 + sg*16];
        float4 q1 = *(float4*)&sm[MSGR + row*36 + sg*16 + 4];
        float4 q2 = *(float4*)&sm[MSGR + row*36 + sg*16 + 8];
        float4 q3 = *(float4*)&sm[MSGR + row*36 + sg*16 + 12];
        float ss = q0.x*q0.x+q0.y*q0.y+q0.z*q0.z+q0.w*q0.w
                 + q1.x*q1.x+q1.y*q1.y+q1.z*q1.z+q1.w*q1.w
                 + q2.x*q2.x+q2.y*q2.y+q2.z*q2.z+q2.w*q2.w
                 + q3.x*q3.x+q3.y*q3.y+q3.z*q3.z+q3.w*q3.w;
        ss += __shfl_xor_sync(~0u, ss, 1);
        float inv = 1.0f / fmaxf(sqrtf(ss), 1e-12f);
        float4* og = (float4*)(out + (r0 + row)*32 + sg*16);
        og[0] = make_float4(q0.x*inv, q0.y*inv, q0.z*inv, q0.w*inv);
        og[1] = make_float4(q1.x*inv, q1.y*inv, q1.z*inv, q1.w*inv);
        og[2] = make_float4(q2.x*inv, q2.y*inv, q2.z*inv, q2.w*inv);
        og[3] = make_float4(q3.x*inv, q3.y*inv, q3.z*inv, q3.w*inv);
    }
    __syncthreads();

    // ---------------- action L1: h1 in regs (m128n32), per-warp k32 pipeline ----------
    float h1a[8][4][4];
    #pragma unroll
    for (int s = 0; s < 8; s++)
        #pragma unroll
        for (int t = 0; t < 4; t++)
            h1a[s][t][0]=h1a[s][t][1]=h1a[s][t][2]=h1a[s][t][3]=0.f;
    #pragma unroll
    for (int q = 0; q < 8; q++) {
        const float* nsrc = (q < 7) ? (wsl1 + (q+1)*32) : wsl2;
        ldq(sbu + BUF(wid,(q+1)&1)*4, nsrc, lane);
        CPWAIT1();
        mma128(h1a, sm + XMF + q*32, sm + BUF(wid, q&1));
    }
    __syncthreads();
    #pragma unroll
    for (int s = 0; s < 8; s++)
        #pragma unroll
        for (int t = 0; t < 4; t++) {
            int cb = nb + t*8 + 2*l4, r = s*16 + g;
            float ba = sm[PB1+cb], bb = sm[PB1+cb+1];
            *(float2*)&sm[XMF + r*260 + cb] =
                make_float2(rt(fmaxf(h1a[s][t][0]+ba,0.f)), rt(fmaxf(h1a[s][t][1]+bb,0.f)));
            *(float2*)&sm[XMF + (r+8)*260 + cb] =
                make_float2(rt(fmaxf(h1a[s][t][2]+ba,0.f)), rt(fmaxf(h1a[s][t][3]+bb,0.f)));
        }
    __syncthreads();

    // ---------------- action L2: fused w3 dot, h2 never stored ----------------
    float acl[8][4][4];
    #pragma unroll
    for (int s = 0; s < 8; s++)
        #pragma unroll
        for (int t = 0; t < 4; t++)
            acl[s][t][0]=acl[s][t][1]=acl[s][t][2]=acl[s][t][3]=0.f;
    #pragma unroll
    for (int q = 0; q < 8; q++) {
        if (q < 7) { ldq(sbu + BUF(wid,(q+1)&1)*4, wsl2 + (q+1)*32, lane); CPWAIT1(); }
        else       { CPWAIT0(); }
        mma128(acl, sm + XMF + q*32, sm + BUF(wid, q&1));
    }
    float pr[16];
    #pragma unroll
    for (int i = 0; i < 16; i++) pr[i] = 0.f;
    #pragma unroll
    for (int s = 0; s < 8; s++)
        #pragma unroll
        for (int t = 0; t < 4; t++) {
            int cb = nb + t*8 + 2*l4;
            float ba = sm[PB2+cb], bb = sm[PB2+cb+1];
            float wa = sm[PW3+cb], wb = sm[PW3+cb+1];
            pr[2*s]   += fmaxf(acl[s][t][0]+ba,0.f)*wa + fmaxf(acl[s][t][1]+bb,0.f)*wb;
            pr[2*s+1] += fmaxf(acl[s][t][2]+ba,0.f)*wa + fmaxf(acl[s][t][3]+bb,0.f)*wb;
        }
    #pragma unroll
    for (int i = 0; i < 16; i++) {
        pr[i] += __shfl_xor_sync(~0u, pr[i], 1);
        pr[i] += __shfl_xor_sync(~0u, pr[i], 2);
    }
    if (l4 == 0) {
        #pragma unroll
        for (int s = 0; s < 8; s++) {
            atomicAdd(&sm[SMACT + s*16 + g],     pr[2*s]);
            atomicAdd(&sm[SMACT + s*16 + 8 + g], pr[2*s+1]);
        }
    }
    __syncthreads();
    if (tid < 128)
        out[(long)Bn*32 + r0 + tid] = tanhf(sm[SMACT+tid] + sm[PB3]);
}

extern "C" void kernel_launch(void* const* d_in, const int* in_sizes, int n_in,
                              void* d_out, int out_size) {
    const float* x   = (const float*)d_in[0];
    const float* m   = (const float*)d_in[1];
    const float* f1w = (const float*)d_in[2];
    const float* f1b = (const float*)d_in[3];
    const float* f2w = (const float*)d_in[4];
    const float* f2b = (const float*)d_in[5];
    const float* f3w = (const float*)d_in[6];
    const float* f3b = (const float*)d_in[7];
    const float* w1  = (const float*)d_in[8];
    const float* b1  = (const float*)d_in[9];
    const float* w2  = (const float*)d_in[10];
    const float* b2  = (const float*)d_in[11];
    const float* w3  = (const float*)d_in[12];
    const float* b3  = (const float*)d_in[13];
    float* out = (float*)d_out;

    int Bn = in_sizes[0] / 128;
    prep_weights<<<128, 256>>>(f1w, f2w, f3w, w1, w2);
    cudaFuncSetAttribute(actor_kernel, cudaFuncAttributeMaxDynamicSharedMemorySize, SMEMB);
    actor_kernel<<<Bn / 128, 256, SMEMB>>>(x, m, f1b, f2b, f3b,
                                           b1, b2, w3, b3, out, Bn);
}